// round 1
// baseline (speedup 1.0000x reference)
#include <cuda_runtime.h>
#include <cstdint>

// Problem dims (fixed by reference)
#define N_OUT   11008
#define K_IN    4096
#define T_TOK   32
#define GROUP   128

// Tiling
#define KSPLIT  16
#define KCHUNK  (K_IN / KSPLIT)            // 256 (= 2 groups of 128)
#define THREADS 128
#define CPT     4                          // columns per thread
#define COLS_PER_CTA (THREADS * CPT)       // 512
#define NBLOCKS ((N_OUT + COLS_PER_CTA - 1) / COLS_PER_CTA)  // 22

// Split-K partial accumulator scratch (static device array: no allocations)
__device__ float g_part[KSPLIT * T_TOK * N_OUT];

// f32x2 packed FMA (Blackwell): d.lo = a.lo*b.lo+c.lo ; d.hi = a.hi*b.hi+c.hi
#define FMA2(d, a, b, c) \
    asm("fma.rn.f32x2 %0, %1, %2, %3;" : "=l"(d) : "l"(a), "l"(b), "l"(c))
#define PACK2(out, f) \
    asm("mov.b64 %0, {%1, %1};" : "=l"(out) : "f"(f))

__device__ __forceinline__ float lo32(unsigned long long v) {
    return __uint_as_float((unsigned)(v & 0xffffffffull));
}
__device__ __forceinline__ float hi32(unsigned long long v) {
    return __uint_as_float((unsigned)(v >> 32));
}

__global__ __launch_bounds__(THREADS)
void awq_main(const float* __restrict__ x,
              const int*   __restrict__ qw,
              const int*   __restrict__ qz,
              const float* __restrict__ sc)
{
    // x chunk transposed: X[kk][t]; pad row to 34 floats (even -> 8B-aligned
    // f32x2 loads; stride 34 mod 32 = 2 -> only 2-way STS conflicts on fill)
    __shared__ __align__(16) float X[KCHUNK][T_TOK + 2];

    const int nb = blockIdx.x;
    const int ks = blockIdx.y;
    const int k0 = ks * KCHUNK;

    // ---- cooperative fill of X (vectorized along k, transposed store) ----
    // 8192 floats = 2048 float4; 16 iters of 128 threads
    for (int j = threadIdx.x; j < (KCHUNK * T_TOK) / 4; j += THREADS) {
        int kk = (j % (KCHUNK / 4)) * 4;
        int t  = j / (KCHUNK / 4);
        float4 v = *reinterpret_cast<const float4*>(&x[t * K_IN + k0 + kk]);
        X[kk + 0][t] = v.x;
        X[kk + 1][t] = v.y;
        X[kk + 2][t] = v.z;
        X[kk + 3][t] = v.w;
    }
    __syncthreads();

    const int n0 = nb * COLS_PER_CTA + threadIdx.x * CPT;
    if (n0 >= N_OUT) return;   // N_OUT % 4 == 0, so n0 < N_OUT => n0+3 < N_OUT

    // 4 cols x 16 token-pairs of f32x2 accumulators
    unsigned long long acc[CPT][T_TOK / 2];
#pragma unroll
    for (int j = 0; j < CPT; j++)
#pragma unroll
        for (int p = 0; p < T_TOK / 2; p++)
            acc[j][p] = 0ull;

#pragma unroll 1
    for (int g2 = 0; g2 < KCHUNK / GROUP; g2++) {
        const int g = k0 / GROUP + g2;
        // group constants: w = (q - z) * s = q*s + (-z*s)
        const int4   z4 = *reinterpret_cast<const int4*>(&qz[g * N_OUT + n0]);
        const float4 s4 = *reinterpret_cast<const float4*>(&sc[g * N_OUT + n0]);
        const float c0x = -(float)z4.x * s4.x;
        const float c0y = -(float)z4.y * s4.y;
        const float c0z = -(float)z4.z * s4.z;
        const float c0w = -(float)z4.w * s4.w;

#pragma unroll 2
        for (int kk2 = 0; kk2 < GROUP; kk2++) {
            const int kk = g2 * GROUP + kk2;
            const int4 q = *reinterpret_cast<const int4*>(
                &qw[(size_t)(k0 + kk) * N_OUT + n0]);

            const float w0 = fmaf((float)q.x, s4.x, c0x);
            const float w1 = fmaf((float)q.y, s4.y, c0y);
            const float w2 = fmaf((float)q.z, s4.z, c0z);
            const float w3 = fmaf((float)q.w, s4.w, c0w);
            unsigned long long wp0, wp1, wp2, wp3;
            PACK2(wp0, w0);
            PACK2(wp1, w1);
            PACK2(wp2, w2);
            PACK2(wp3, w3);

#pragma unroll
            for (int p = 0; p < T_TOK / 2; p++) {
                const unsigned long long xp =
                    *reinterpret_cast<const unsigned long long*>(&X[kk][2 * p]);
                FMA2(acc[0][p], wp0, xp, acc[0][p]);
                FMA2(acc[1][p], wp1, xp, acc[1][p]);
                FMA2(acc[2][p], wp2, xp, acc[2][p]);
                FMA2(acc[3][p], wp3, xp, acc[3][p]);
            }
        }
    }

    // ---- write partials: g_part[ks][t][n0..n0+3] ----
    float* part = &g_part[((size_t)ks * T_TOK) * N_OUT];
#pragma unroll
    for (int p = 0; p < T_TOK / 2; p++) {
        float4 lo4, hi4;
        lo4.x = lo32(acc[0][p]); lo4.y = lo32(acc[1][p]);
        lo4.z = lo32(acc[2][p]); lo4.w = lo32(acc[3][p]);
        hi4.x = hi32(acc[0][p]); hi4.y = hi32(acc[1][p]);
        hi4.z = hi32(acc[2][p]); hi4.w = hi32(acc[3][p]);
        *reinterpret_cast<float4*>(&part[(size_t)(2 * p + 0) * N_OUT + n0]) = lo4;
        *reinterpret_cast<float4*>(&part[(size_t)(2 * p + 1) * N_OUT + n0]) = hi4;
    }
}

__global__ __launch_bounds__(256)
void awq_reduce(const float* __restrict__ bias, float* __restrict__ out)
{
    const int total4 = (T_TOK * N_OUT) / 4;  // 88064
    int i = blockIdx.x * blockDim.x + threadIdx.x;
    if (i >= total4) return;
    const int n4 = i % (N_OUT / 4);

    float4 s = reinterpret_cast<const float4*>(bias)[n4];
    const float4* part4 = reinterpret_cast<const float4*>(g_part);
#pragma unroll
    for (int sp = 0; sp < KSPLIT; sp++) {
        float4 v = part4[(size_t)sp * total4 + i];
        s.x += v.x; s.y += v.y; s.z += v.z; s.w += v.w;
    }
    reinterpret_cast<float4*>(out)[i] = s;
}

extern "C" void kernel_launch(void* const* d_in, const int* in_sizes, int n_in,
                              void* d_out, int out_size)
{
    const float* x    = (const float*)d_in[0];
    const int*   qw   = (const int*)  d_in[1];
    const int*   qz   = (const int*)  d_in[2];
    const float* sc   = (const float*)d_in[3];
    const float* bias = (const float*)d_in[4];
    float*       out  = (float*)d_out;

    dim3 grid(NBLOCKS, KSPLIT);
    awq_main<<<grid, THREADS>>>(x, qw, qz, sc);

    const int total4 = (T_TOK * N_OUT) / 4;
    awq_reduce<<<(total4 + 255) / 256, 256>>>(bias, out);
}

// round 2
// speedup vs baseline: 1.7255x; 1.7255x over previous
#include <cuda_runtime.h>
#include <cstdint>

// Problem dims (fixed by reference)
#define N_OUT   11008
#define K_IN    4096
#define T_TOK   32
#define GROUP   128

// Tiling
#define KSPLIT  16
#define KCHUNK  (K_IN / KSPLIT)            // 256 (= 2 groups of 128)
#define THREADS 128
#define CPT     2                          // columns per thread
#define COLS_PER_CTA (THREADS * CPT)       // 256
#define NBLOCKS (N_OUT / COLS_PER_CTA)     // 43 (exact: 43*256 = 11008)

// Split-K partial accumulator scratch (static device array: no allocations)
__device__ float g_part[KSPLIT * T_TOK * N_OUT];

// f32x2 packed FMA (Blackwell): d.lo = a.lo*b.lo+c.lo ; d.hi = a.hi*b.hi+c.hi
#define FMA2(d, a, b, c) \
    asm("fma.rn.f32x2 %0, %1, %2, %3;" : "=l"(d) : "l"(a), "l"(b), "l"(c))
#define PACK2(out, f) \
    asm("mov.b64 %0, {%1, %1};" : "=l"(out) : "f"(f))

__device__ __forceinline__ float lo32(unsigned long long v) {
    return __uint_as_float((unsigned)(v & 0xffffffffull));
}
__device__ __forceinline__ float hi32(unsigned long long v) {
    return __uint_as_float((unsigned)(v >> 32));
}

__global__ __launch_bounds__(THREADS, 4)
void awq_main(const float* __restrict__ x,
              const int*   __restrict__ qw,
              const int*   __restrict__ qz,
              const float* __restrict__ sc)
{
    // x chunk transposed: X[kk][t], row stride 32 floats = 128B (16B aligned
    // rows -> LDS.128 broadcast reads; broadcasts are conflict-free by def).
    __shared__ __align__(16) float X[KCHUNK][T_TOK];   // 32 KB

    const int nb = blockIdx.x;
    const int ks = blockIdx.y;
    const int k0 = ks * KCHUNK;

    // ---- cooperative fill of X (vectorized along k, transposed store) ----
    for (int j = threadIdx.x; j < (KCHUNK * T_TOK) / 4; j += THREADS) {
        int kk = (j % (KCHUNK / 4)) * 4;
        int t  = j / (KCHUNK / 4);
        float4 v = *reinterpret_cast<const float4*>(&x[t * K_IN + k0 + kk]);
        X[kk + 0][t] = v.x;
        X[kk + 1][t] = v.y;
        X[kk + 2][t] = v.z;
        X[kk + 3][t] = v.w;
    }
    __syncthreads();

    const int n0 = nb * COLS_PER_CTA + threadIdx.x * CPT;  // always in-bounds

    // 2 cols x 16 token-pairs of f32x2 accumulators (64 regs)
    unsigned long long acc[CPT][T_TOK / 2];
#pragma unroll
    for (int j = 0; j < CPT; j++)
#pragma unroll
        for (int p = 0; p < T_TOK / 2; p++)
            acc[j][p] = 0ull;

    // ---- depth-3 register ring prefetch of q ----
    const int* qbase = qw + (size_t)k0 * N_OUT + n0;
    int2 qr0 = *reinterpret_cast<const int2*>(qbase);
    int2 qr1 = *reinterpret_cast<const int2*>(qbase + N_OUT);
    int2 qr2 = *reinterpret_cast<const int2*>(qbase + 2 * (size_t)N_OUT);
    int kload = 3;

#pragma unroll 1
    for (int g2 = 0; g2 < KCHUNK / GROUP; g2++) {
        const int g = k0 / GROUP + g2;
        // group constants: w = (q - z) * s = q*s + (-z*s)
        const int2   z2 = *reinterpret_cast<const int2*>(&qz[g * N_OUT + n0]);
        const float2 s2 = *reinterpret_cast<const float2*>(&sc[g * N_OUT + n0]);
        const float c0 = -(float)z2.x * s2.x;
        const float c1 = -(float)z2.y * s2.y;

#pragma unroll 4
        for (int kk2 = 0; kk2 < GROUP; kk2++) {
            const int2 qc = qr0;
            qr0 = qr1;
            qr1 = qr2;
            // clamp keeps address in-bounds; tail reloads last row harmlessly
            const int kl = (kload < KCHUNK) ? kload : (KCHUNK - 1);
            qr2 = *reinterpret_cast<const int2*>(qbase + (size_t)kl * N_OUT);
            kload++;

            const float w0 = fmaf((float)qc.x, s2.x, c0);
            const float w1 = fmaf((float)qc.y, s2.y, c1);
            unsigned long long wp0, wp1;
            PACK2(wp0, w0);
            PACK2(wp1, w1);

            const int kk = g2 * GROUP + kk2;
            const ulonglong2* xrow =
                reinterpret_cast<const ulonglong2*>(&X[kk][0]);
#pragma unroll
            for (int q4 = 0; q4 < T_TOK / 4; q4++) {   // 8 x LDS.128 broadcast
                const ulonglong2 xp2 = xrow[q4];
                FMA2(acc[0][2 * q4 + 0], wp0, xp2.x, acc[0][2 * q4 + 0]);
                FMA2(acc[1][2 * q4 + 0], wp1, xp2.x, acc[1][2 * q4 + 0]);
                FMA2(acc[0][2 * q4 + 1], wp0, xp2.y, acc[0][2 * q4 + 1]);
                FMA2(acc[1][2 * q4 + 1], wp1, xp2.y, acc[1][2 * q4 + 1]);
            }
        }
    }

    // ---- write partials: g_part[ks][t][n0..n0+1] ----
    float* part = &g_part[(size_t)ks * T_TOK * N_OUT + n0];
#pragma unroll
    for (int p = 0; p < T_TOK / 2; p++) {
        float2 lo, hi;
        lo.x = lo32(acc[0][p]); lo.y = lo32(acc[1][p]);
        hi.x = hi32(acc[0][p]); hi.y = hi32(acc[1][p]);
        *reinterpret_cast<float2*>(&part[(size_t)(2 * p + 0) * N_OUT]) = lo;
        *reinterpret_cast<float2*>(&part[(size_t)(2 * p + 1) * N_OUT]) = hi;
    }
}

__global__ __launch_bounds__(256)
void awq_reduce(const float* __restrict__ bias, float* __restrict__ out)
{
    const int total4 = (T_TOK * N_OUT) / 4;  // 88064
    int i = blockIdx.x * blockDim.x + threadIdx.x;
    if (i >= total4) return;
    const int n4 = i % (N_OUT / 4);

    float4 s = reinterpret_cast<const float4*>(bias)[n4];
    const float4* part4 = reinterpret_cast<const float4*>(g_part);
#pragma unroll
    for (int sp = 0; sp < KSPLIT; sp++) {
        float4 v = part4[(size_t)sp * total4 + i];
        s.x += v.x; s.y += v.y; s.z += v.z; s.w += v.w;
    }
    reinterpret_cast<float4*>(out)[i] = s;
}

extern "C" void kernel_launch(void* const* d_in, const int* in_sizes, int n_in,
                              void* d_out, int out_size)
{
    const float* x    = (const float*)d_in[0];
    const int*   qw   = (const int*)  d_in[1];
    const int*   qz   = (const int*)  d_in[2];
    const float* sc   = (const float*)d_in[3];
    const float* bias = (const float*)d_in[4];
    float*       out  = (float*)d_out;

    dim3 grid(NBLOCKS, KSPLIT);
    awq_main<<<grid, THREADS>>>(x, qw, qz, sc);

    const int total4 = (T_TOK * N_OUT) / 4;
    awq_reduce<<<(total4 + 255) / 256, 256>>>(bias, out);
}

// round 5
// speedup vs baseline: 2.9016x; 1.6816x over previous
#include <cuda_runtime.h>
#include <cuda_bf16.h>
#include <cstdint>

// ---------------- problem dims ----------------
#define N_OUT   11008
#define K_IN    4096
#define T_TOK   32
#define GROUP   128

// ---------------- tiling ----------------
#define KSPLIT  8
#define GPC     4                       // groups per CTA: 8*4*128 = 4096 = K_IN
#define NTILE   128
#define NBLK    (N_OUT / NTILE)         // 86
#define THREADS 256                     // 8 warps, each owns n-slice of 16

// ---------------- smem layout (byte offsets into dynamic smem) ----------------
// A: 32 rows x 264 bf16 (528 B rows; cols 0-127 = x_hi, 128-255 = x_lo)
// B: 128 rows x 136 bf16 (272 B rows; [k][n], n contiguous)
// RAW: 128 rows x 128 int32 (512 B rows), cp.async staging
#define AOFF    0
#define A_SZ    (32 * 264 * 2)          // 16896
#define BOFF    A_SZ                    // 16896 (16B aligned)
#define B_SZ    (128 * 136 * 2)         // 34816
#define RAWOFF  (AOFF + A_SZ + B_SZ)    // 51712
#define RAW_SZ  (128 * 128 * 4)         // 65536
#define SMEM_DYN (RAWOFF + RAW_SZ)      // 117248

__device__ float g_part[KSPLIT * T_TOK * N_OUT];

// ---------------- PTX helpers ----------------
__device__ __forceinline__ uint32_t smem_u32(const void* p) {
    uint32_t a;
    asm("{ .reg .u64 t; cvta.to.shared.u64 t, %1; cvt.u32.u64 %0, t; }"
        : "=r"(a) : "l"(p));
    return a;
}
#define CP_ASYNC16(dst, src) \
    asm volatile("cp.async.cg.shared.global [%0], [%1], 16;" :: "r"(dst), "l"(src) : "memory")
#define CP_COMMIT() asm volatile("cp.async.commit_group;" ::: "memory")
#define CP_WAIT0()  asm volatile("cp.async.wait_group 0;" ::: "memory")

#define LDSMX4(r, addr) \
    asm volatile("ldmatrix.sync.aligned.m8n8.x4.shared.b16 {%0,%1,%2,%3}, [%4];" \
        : "=r"((r)[0]), "=r"((r)[1]), "=r"((r)[2]), "=r"((r)[3]) : "r"(addr))
#define LDSMX4T(r, addr) \
    asm volatile("ldmatrix.sync.aligned.m8n8.x4.trans.shared.b16 {%0,%1,%2,%3}, [%4];" \
        : "=r"((r)[0]), "=r"((r)[1]), "=r"((r)[2]), "=r"((r)[3]) : "r"(addr))

#define MMA16816(d, a, b0, b1) \
    asm volatile("mma.sync.aligned.m16n8k16.row.col.f32.bf16.bf16.f32 " \
        "{%0,%1,%2,%3}, {%4,%5,%6,%7}, {%8,%9}, {%0,%1,%2,%3};" \
        : "+f"((d)[0]), "+f"((d)[1]), "+f"((d)[2]), "+f"((d)[3]) \
        : "r"((a)[0]), "r"((a)[1]), "r"((a)[2]), "r"((a)[3]), "r"(b0), "r"(b1))

__device__ __forceinline__ void prefetch_group(uint32_t RAW, const int* __restrict__ qw,
                                               int g, int n0, int tid)
{
#pragma unroll
    for (int i = 0; i < 16; i++) {
        int idx = tid + THREADS * i;                  // 0..4095
        int kk = idx >> 5, seg = idx & 31;
        uint32_t dst = RAW + kk * 512 + seg * 16;
        const int* src = qw + (size_t)(g * GROUP + kk) * N_OUT + n0 + seg * 4;
        CP_ASYNC16(dst, src);
    }
    CP_COMMIT();
}

__global__ __launch_bounds__(THREADS, 1)
void awq_mma(const float* __restrict__ x,
             const int*   __restrict__ qw,
             const int*   __restrict__ qz,
             const float* __restrict__ sc)
{
    extern __shared__ __align__(16) char smem[];
    const uint32_t sb  = smem_u32(smem);
    const uint32_t A   = sb + AOFF;
    const uint32_t B   = sb + BOFF;
    const uint32_t RAW = sb + RAWOFF;

    const int tid  = threadIdx.x;
    const int lane = tid & 31;
    const int w    = tid >> 5;          // warp 0..7, n-slice w*16
    const int n0   = blockIdx.x * NTILE;
    const int ks   = blockIdx.y;

    // prefetch raw q tile for group 0
    prefetch_group(RAW, qw, ks * GPC, n0, tid);

    // ldmatrix lane base addresses
    // A (row-major [m][k], 528B rows): lane 0-15 -> rows m0-15 (k bytes 0-15),
    // lane 16-31 -> rows m0-15 at +16B. Per k-step j: +j*32B; mtile 1: +16*528.
    const uint32_t a_lane = A + (uint32_t)(lane & 15) * 528u + (uint32_t)(lane >> 4) * 16u;
    // B trans ([k][n] 272B rows): lanes (grp&1)*8+r -> k rows, (lane>>4)*8 -> +n8.
    const uint32_t b_lane = B + (uint32_t)(((lane >> 3) & 1) * 8 + (lane & 7)) * 272u
                              + (uint32_t)(w * 16 + (lane >> 4) * 8) * 2u;

    float master[2][2][4];
#pragma unroll
    for (int mt = 0; mt < 2; mt++)
#pragma unroll
        for (int nt = 0; nt < 2; nt++)
#pragma unroll
            for (int r = 0; r < 4; r++) master[mt][nt][r] = 0.0f;

    for (int gi = 0; gi < GPC; gi++) {
        const int g = ks * GPC + gi;

        CP_WAIT0();
        __syncthreads();   // RAW ready; also orders prev-iter mma reads vs B/A rewrite

        // ---- convert RAW int32 [k][n] -> B bf16 [k][n] (w = q - z) ----
        {
            const int nseg = tid & 31;              // columns nseg*4..+3
            const int krow = tid >> 5;              // rows krow, krow+8, ...
            const int4 z4 = *reinterpret_cast<const int4*>(
                qz + (size_t)g * N_OUT + n0 + nseg * 4);
            const char* rawc = smem + RAWOFF + krow * 512 + nseg * 16;
            char*       bc   = smem + BOFF   + krow * 272 + nseg * 8;
#pragma unroll
            for (int it = 0; it < 16; it++) {
                int4 q = *reinterpret_cast<const int4*>(rawc + it * (8 * 512));
                __nv_bfloat162 p0 = __floats2bfloat162_rn((float)(q.x - z4.x),
                                                          (float)(q.y - z4.y));
                __nv_bfloat162 p1 = __floats2bfloat162_rn((float)(q.z - z4.z),
                                                          (float)(q.w - z4.w));
                uint2 pk;
                pk.x = reinterpret_cast<uint32_t&>(p0);
                pk.y = reinterpret_cast<uint32_t&>(p1);
                *reinterpret_cast<uint2*>(bc + it * (8 * 272)) = pk;
            }
        }

        // ---- fill A: x split hi|lo along K (rows=tokens, 528B rows) ----
        {
            const int t = tid >> 3, seg = tid & 7;  // token, 16-col segment
            const float4* xp = reinterpret_cast<const float4*>(
                x + (size_t)t * K_IN + g * GROUP + seg * 16);
            char* ar = smem + AOFF + t * 528;
#pragma unroll
            for (int q4 = 0; q4 < 4; q4++) {
                float4 v = xp[q4];
                __nv_bfloat162 h0 = __floats2bfloat162_rn(v.x, v.y);
                __nv_bfloat162 h1 = __floats2bfloat162_rn(v.z, v.w);
                __nv_bfloat162 l0 = __floats2bfloat162_rn(
                    v.x - __bfloat162float(h0.x), v.y - __bfloat162float(h0.y));
                __nv_bfloat162 l1 = __floats2bfloat162_rn(
                    v.z - __bfloat162float(h1.x), v.w - __bfloat162float(h1.y));
                uint2 hp, lp;
                hp.x = reinterpret_cast<uint32_t&>(h0);
                hp.y = reinterpret_cast<uint32_t&>(h1);
                lp.x = reinterpret_cast<uint32_t&>(l0);
                lp.y = reinterpret_cast<uint32_t&>(l1);
                const int cb = seg * 32 + q4 * 8;   // byte offset of 4 bf16
                *reinterpret_cast<uint2*>(ar + cb) = hp;          // hi: cols 0-127
                *reinterpret_cast<uint2*>(ar + 256 + cb) = lp;    // lo: cols 128-255
            }
        }
        __syncthreads();

        // ---- prefetch next group's raw tile (overlaps MMA below) ----
        if (gi + 1 < GPC)
            prefetch_group(RAW, qw, g + 1, n0, tid);

        // ---- MMA: 16 k-steps (8 hi + 8 lo; B reused for both halves) ----
        float gacc[2][2][4];
#pragma unroll
        for (int mt = 0; mt < 2; mt++)
#pragma unroll
            for (int nt = 0; nt < 2; nt++)
#pragma unroll
                for (int r = 0; r < 4; r++) gacc[mt][nt][r] = 0.0f;

#pragma unroll
        for (int j = 0; j < 16; j++) {
            uint32_t a0[4], a1[4], b[4];
            LDSMX4(a0, a_lane + j * 32);
            LDSMX4(a1, a_lane + 16 * 528 + j * 32);
            LDSMX4T(b, b_lane + (j & 7) * (16 * 272));
            MMA16816(gacc[0][0], a0, b[0], b[1]);
            MMA16816(gacc[0][1], a0, b[2], b[3]);
            MMA16816(gacc[1][0], a1, b[0], b[1]);
            MMA16816(gacc[1][1], a1, b[2], b[3]);
        }

        // ---- per-group scale into master acc ----
#pragma unroll
        for (int nt = 0; nt < 2; nt++) {
            const int nn = n0 + w * 16 + nt * 8 + (lane & 3) * 2;
            const float2 s2 = *reinterpret_cast<const float2*>(
                sc + (size_t)g * N_OUT + nn);
#pragma unroll
            for (int mt = 0; mt < 2; mt++) {
                master[mt][nt][0] = fmaf(s2.x, gacc[mt][nt][0], master[mt][nt][0]);
                master[mt][nt][1] = fmaf(s2.y, gacc[mt][nt][1], master[mt][nt][1]);
                master[mt][nt][2] = fmaf(s2.x, gacc[mt][nt][2], master[mt][nt][2]);
                master[mt][nt][3] = fmaf(s2.y, gacc[mt][nt][3], master[mt][nt][3]);
            }
        }
    }

    // ---- write split-K partials ----
    // d-frag mapping: rows m = lane>>2 (+8 for regs 2,3), cols n = (lane&3)*2 (+1)
    const int mrow = lane >> 2;
#pragma unroll
    for (int mt = 0; mt < 2; mt++)
#pragma unroll
        for (int nt = 0; nt < 2; nt++) {
            const int nn = n0 + w * 16 + nt * 8 + (lane & 3) * 2;
            float* p = g_part + ((size_t)ks * T_TOK + mt * 16 + mrow) * N_OUT + nn;
            *reinterpret_cast<float2*>(p) =
                make_float2(master[mt][nt][0], master[mt][nt][1]);
            *reinterpret_cast<float2*>(p + (size_t)8 * N_OUT) =
                make_float2(master[mt][nt][2], master[mt][nt][3]);
        }
}

__global__ __launch_bounds__(256)
void awq_reduce(const float* __restrict__ bias, float* __restrict__ out)
{
    const int total4 = (T_TOK * N_OUT) / 4;  // 88064
    int i = blockIdx.x * blockDim.x + threadIdx.x;
    if (i >= total4) return;
    const int n4 = i % (N_OUT / 4);

    float4 s = reinterpret_cast<const float4*>(bias)[n4];
    const float4* part4 = reinterpret_cast<const float4*>(g_part);
#pragma unroll
    for (int sp = 0; sp < KSPLIT; sp++) {
        float4 v = part4[(size_t)sp * total4 + i];
        s.x += v.x; s.y += v.y; s.z += v.z; s.w += v.w;
    }
    reinterpret_cast<float4*>(out)[i] = s;
}

extern "C" void kernel_launch(void* const* d_in, const int* in_sizes, int n_in,
                              void* d_out, int out_size)
{
    const float* x    = (const float*)d_in[0];
    const int*   qw   = (const int*)  d_in[1];
    const int*   qz   = (const int*)  d_in[2];
    const float* sc   = (const float*)d_in[3];
    const float* bias = (const float*)d_in[4];
    float*       out  = (float*)d_out;

    static bool attr_done = false;
    if (!attr_done) {
        cudaFuncSetAttribute(awq_mma, cudaFuncAttributeMaxDynamicSharedMemorySize,
                             SMEM_DYN);
        attr_done = true;
    }

    dim3 grid(NBLK, KSPLIT);
    awq_mma<<<grid, THREADS, SMEM_DYN>>>(x, qw, qz, sc);

    const int total4 = (T_TOK * N_OUT) / 4;
    awq_reduce<<<(total4 + 255) / 256, 256>>>(bias, out);
}

// round 6
// speedup vs baseline: 3.1593x; 1.0888x over previous
#include <cuda_runtime.h>
#include <cuda_bf16.h>
#include <cstdint>

// ---------------- problem dims ----------------
#define N_OUT   11008
#define K_IN    4096
#define T_TOK   32
#define GROUP   128

// ---------------- tiling ----------------
#define KSPLIT  8
#define GPC     4                       // groups per CTA: 8*4*128 = 4096 = K_IN
#define NTILE   128
#define NBLK    (N_OUT / NTILE)         // 86
#define THREADS 256                     // 8 warps, each owns n-slice of 16

// ---------------- smem layout ----------------
// A buffers: 2 x (32 rows x 264 bf16, 528B pitch; cols 0-127 hi, 128-255 lo)
// B buffers: 2 x (128 rows x 136 bf16, 272B pitch; [k][n])
#define A_SZ1   (32 * 264 * 2)          // 16896
#define BOFF    (2 * A_SZ1)             // 33792
#define B_SZ1   (128 * 136 * 2)         // 34816
#define SMEM_DYN (BOFF + 2 * B_SZ1)     // 103424  -> 2 CTAs/SM

__device__ float g_part[KSPLIT * T_TOK * N_OUT];
// pre-split x: [t][half][k] bf16 (half 0 = hi, 1 = lo)
__device__ __nv_bfloat16 g_xs[T_TOK * 2 * K_IN];

// ---------------- PTX helpers ----------------
__device__ __forceinline__ uint32_t smem_u32(const void* p) {
    uint32_t a;
    asm("{ .reg .u64 t; cvta.to.shared.u64 t, %1; cvt.u32.u64 %0, t; }"
        : "=r"(a) : "l"(p));
    return a;
}
#define CP_ASYNC16(dst, src) \
    asm volatile("cp.async.cg.shared.global [%0], [%1], 16;" :: "r"(dst), "l"(src) : "memory")
#define CP_COMMIT() asm volatile("cp.async.commit_group;" ::: "memory")
#define CP_WAIT0()  asm volatile("cp.async.wait_group 0;" ::: "memory")

#define LDSMX4(r, addr) \
    asm volatile("ldmatrix.sync.aligned.m8n8.x4.shared.b16 {%0,%1,%2,%3}, [%4];" \
        : "=r"((r)[0]), "=r"((r)[1]), "=r"((r)[2]), "=r"((r)[3]) : "r"(addr))
#define LDSMX4T(r, addr) \
    asm volatile("ldmatrix.sync.aligned.m8n8.x4.trans.shared.b16 {%0,%1,%2,%3}, [%4];" \
        : "=r"((r)[0]), "=r"((r)[1]), "=r"((r)[2]), "=r"((r)[3]) : "r"(addr))

#define MMA16816(d, a, b0, b1) \
    asm volatile("mma.sync.aligned.m16n8k16.row.col.f32.bf16.bf16.f32 " \
        "{%0,%1,%2,%3}, {%4,%5,%6,%7}, {%8,%9}, {%0,%1,%2,%3};" \
        : "+f"((d)[0]), "+f"((d)[1]), "+f"((d)[2]), "+f"((d)[3]) \
        : "r"((a)[0]), "r"((a)[1]), "r"((a)[2]), "r"((a)[3]), "r"(b0), "r"(b1))

// ---------------- pre-kernel: split x into bf16 hi/lo ----------------
__global__ __launch_bounds__(256)
void awq_split(const float* __restrict__ x)
{
    int i = blockIdx.x * 256 + threadIdx.x;          // < 32768
    int t  = i >> 10;                                // K_IN/4 = 1024 float4 per row
    int k4 = (i & 1023) * 4;
    float4 v = *reinterpret_cast<const float4*>(x + (size_t)t * K_IN + k4);
    __nv_bfloat162 h0 = __floats2bfloat162_rn(v.x, v.y);
    __nv_bfloat162 h1 = __floats2bfloat162_rn(v.z, v.w);
    __nv_bfloat162 l0 = __floats2bfloat162_rn(v.x - __bfloat162float(h0.x),
                                              v.y - __bfloat162float(h0.y));
    __nv_bfloat162 l1 = __floats2bfloat162_rn(v.z - __bfloat162float(h1.x),
                                              v.w - __bfloat162float(h1.y));
    uint2 hp, lp;
    hp.x = reinterpret_cast<uint32_t&>(h0); hp.y = reinterpret_cast<uint32_t&>(h1);
    lp.x = reinterpret_cast<uint32_t&>(l0); lp.y = reinterpret_cast<uint32_t&>(l1);
    *reinterpret_cast<uint2*>(&g_xs[(size_t)(t * 2 + 0) * K_IN + k4]) = hp;
    *reinterpret_cast<uint2*>(&g_xs[(size_t)(t * 2 + 1) * K_IN + k4]) = lp;
}

// ---------------- main kernel ----------------
__global__ __launch_bounds__(THREADS, 2)
void awq_mma(const int*   __restrict__ qw,
             const int*   __restrict__ qz,
             const float* __restrict__ sc)
{
    extern __shared__ __align__(16) char smem[];
    const uint32_t sb = smem_u32(smem);

    const int tid  = threadIdx.x;
    const int lane = tid & 31;
    const int w    = tid >> 5;          // warp 0..7, n-slice w*16
    const int n0   = blockIdx.x * NTILE;
    const int ks   = blockIdx.y;

    // q load geometry: krow = tid>>5 (0..7), col seg = lane (16B)
    const int krow = tid >> 5;
    const int4* qcol = reinterpret_cast<const int4*>(
        qw + (size_t)(ks * GPC * GROUP + krow) * N_OUT + n0) + lane;
    const size_t qrow8 = (size_t)8 * (N_OUT / 4);   // int4 stride for 8 k-rows
    const size_t qgrp  = (size_t)GROUP * (N_OUT / 4);

    // A cp.async geometry (4 chunks per thread)
    // idx: t = idx>>5, seg = idx&31; half = seg>>4; s16 = seg&15
    // dst = Abuf + t*528 + half*256 + s16*16 ; src = g_xs[(t*2+half)*K_IN + g*128 + s16*8]

    // ---- prologue: q LDGs + A cp.async for group 0 ----
    int4 qr[16];
#pragma unroll
    for (int it = 0; it < 16; it++)
        qr[it] = __ldcs(qcol + (size_t)it * qrow8);
    {
        const int g0 = ks * GPC;
#pragma unroll
        for (int i = 0; i < 4; i++) {
            int idx = tid + THREADS * i;
            int t = idx >> 5, seg = idx & 31, half = seg >> 4, s16 = seg & 15;
            uint32_t dst = sb + t * 528 + half * 256 + s16 * 16;
            const __nv_bfloat16* src =
                &g_xs[(size_t)(t * 2 + half) * K_IN + g0 * GROUP + s16 * 8];
            CP_ASYNC16(dst, src);
        }
        CP_COMMIT();
    }

    // ldmatrix lane bases (buffer 0)
    const uint32_t a_lane = sb + (uint32_t)(lane & 15) * 528u
                               + (uint32_t)(lane >> 4) * 16u;
    const uint32_t b_lane = sb + BOFF
        + (uint32_t)(((lane >> 3) & 1) * 8 + (lane & 7)) * 272u
        + (uint32_t)(w * 16 + (lane >> 4) * 8) * 2u;

    float master[2][2][4];
#pragma unroll
    for (int mt = 0; mt < 2; mt++)
#pragma unroll
        for (int nt = 0; nt < 2; nt++)
#pragma unroll
            for (int r = 0; r < 4; r++) master[mt][nt][r] = 0.0f;

    for (int gi = 0; gi < GPC; gi++) {
        const int g   = ks * GPC + gi;
        const int buf = gi & 1;

        // ---- convert qr -> B[buf] bf16 [k][n] (w = q - z) ----
        {
            const int4 z4 = *reinterpret_cast<const int4*>(
                qz + (size_t)g * N_OUT + n0 + lane * 4);
            char* bc = smem + BOFF + buf * B_SZ1 + krow * 272 + lane * 8;
#pragma unroll
            for (int it = 0; it < 16; it++) {
                int4 q = qr[it];
                __nv_bfloat162 p0 = __floats2bfloat162_rn((float)(q.x - z4.x),
                                                          (float)(q.y - z4.y));
                __nv_bfloat162 p1 = __floats2bfloat162_rn((float)(q.z - z4.z),
                                                          (float)(q.w - z4.w));
                uint2 pk;
                pk.x = reinterpret_cast<uint32_t&>(p0);
                pk.y = reinterpret_cast<uint32_t&>(p1);
                *reinterpret_cast<uint2*>(bc + it * (8 * 272)) = pk;
            }
        }

        // ---- issue next group's q LDGs (regs free after convert) ----
        if (gi + 1 < GPC) {
#pragma unroll
            for (int it = 0; it < 16; it++)
                qr[it] = __ldcs(qcol + (size_t)(gi + 1) * qgrp + (size_t)it * qrow8);
        }

        CP_WAIT0();            // A[buf] landed (only pending cp group)
        __syncthreads();       // B[buf] + A[buf] visible; prev MMA drained

        // ---- cp.async A[1-buf] for next group (overlaps MMA below) ----
        if (gi + 1 < GPC) {
            const int gn = g + 1;
            const uint32_t Ab = sb + (1 - buf) * A_SZ1;
#pragma unroll
            for (int i = 0; i < 4; i++) {
                int idx = tid + THREADS * i;
                int t = idx >> 5, seg = idx & 31, half = seg >> 4, s16 = seg & 15;
                uint32_t dst = Ab + t * 528 + half * 256 + s16 * 16;
                const __nv_bfloat16* src =
                    &g_xs[(size_t)(t * 2 + half) * K_IN + gn * GROUP + s16 * 8];
                CP_ASYNC16(dst, src);
            }
            CP_COMMIT();
        }

        // ---- MMA: 16 k-steps (8 hi + 8 lo; B reused for both halves) ----
        float gacc[2][2][4];
#pragma unroll
        for (int mt = 0; mt < 2; mt++)
#pragma unroll
            for (int nt = 0; nt < 2; nt++)
#pragma unroll
                for (int r = 0; r < 4; r++) gacc[mt][nt][r] = 0.0f;

        const uint32_t ab = a_lane + buf * A_SZ1;
        const uint32_t bb = b_lane + buf * B_SZ1;
#pragma unroll
        for (int j = 0; j < 16; j++) {
            uint32_t a0[4], a1[4], b[4];
            LDSMX4(a0, ab + j * 32);
            LDSMX4(a1, ab + 16 * 528 + j * 32);
            LDSMX4T(b, bb + (j & 7) * (16 * 272));
            MMA16816(gacc[0][0], a0, b[0], b[1]);
            MMA16816(gacc[0][1], a0, b[2], b[3]);
            MMA16816(gacc[1][0], a1, b[0], b[1]);
            MMA16816(gacc[1][1], a1, b[2], b[3]);
        }

        // ---- per-group scale into master acc ----
#pragma unroll
        for (int nt = 0; nt < 2; nt++) {
            const int nn = n0 + w * 16 + nt * 8 + (lane & 3) * 2;
            const float2 s2 = *reinterpret_cast<const float2*>(
                sc + (size_t)g * N_OUT + nn);
#pragma unroll
            for (int mt = 0; mt < 2; mt++) {
                master[mt][nt][0] = fmaf(s2.x, gacc[mt][nt][0], master[mt][nt][0]);
                master[mt][nt][1] = fmaf(s2.y, gacc[mt][nt][1], master[mt][nt][1]);
                master[mt][nt][2] = fmaf(s2.x, gacc[mt][nt][2], master[mt][nt][2]);
                master[mt][nt][3] = fmaf(s2.y, gacc[mt][nt][3], master[mt][nt][3]);
            }
        }
    }

    // ---- write split-K partials ----
    const int mrow = lane >> 2;
#pragma unroll
    for (int mt = 0; mt < 2; mt++)
#pragma unroll
        for (int nt = 0; nt < 2; nt++) {
            const int nn = n0 + w * 16 + nt * 8 + (lane & 3) * 2;
            float* p = g_part + ((size_t)ks * T_TOK + mt * 16 + mrow) * N_OUT + nn;
            *reinterpret_cast<float2*>(p) =
                make_float2(master[mt][nt][0], master[mt][nt][1]);
            *reinterpret_cast<float2*>(p + (size_t)8 * N_OUT) =
                make_float2(master[mt][nt][2], master[mt][nt][3]);
        }
}

__global__ __launch_bounds__(256)
void awq_reduce(const float* __restrict__ bias, float* __restrict__ out)
{
    const int total4 = (T_TOK * N_OUT) / 4;  // 88064
    int i = blockIdx.x * blockDim.x + threadIdx.x;
    if (i >= total4) return;
    const int n4 = i % (N_OUT / 4);

    float4 s = reinterpret_cast<const float4*>(bias)[n4];
    const float4* part4 = reinterpret_cast<const float4*>(g_part);
#pragma unroll
    for (int sp = 0; sp < KSPLIT; sp++) {
        float4 v = part4[(size_t)sp * total4 + i];
        s.x += v.x; s.y += v.y; s.z += v.z; s.w += v.w;
    }
    reinterpret_cast<float4*>(out)[i] = s;
}

extern "C" void kernel_launch(void* const* d_in, const int* in_sizes, int n_in,
                              void* d_out, int out_size)
{
    const float* x    = (const float*)d_in[0];
    const int*   qw   = (const int*)  d_in[1];
    const int*   qz   = (const int*)  d_in[2];
    const float* sc   = (const float*)d_in[3];
    const float* bias = (const float*)d_in[4];
    float*       out  = (float*)d_out;

    static bool attr_done = false;
    if (!attr_done) {
        cudaFuncSetAttribute(awq_mma, cudaFuncAttributeMaxDynamicSharedMemorySize,
                             SMEM_DYN);
        attr_done = true;
    }

    awq_split<<<(T_TOK * K_IN / 4 + 255) / 256, 256>>>(x);

    dim3 grid(NBLK, KSPLIT);
    awq_mma<<<grid, THREADS, SMEM_DYN>>>(qw, qz, sc);

    const int total4 = (T_TOK * N_OUT) / 4;
    awq_reduce<<<(total4 + 255) / 256, 256>>>(bias, out);
}

// round 13
// speedup vs baseline: 4.4662x; 1.4137x over previous
#include <cuda_runtime.h>
#include <cuda_fp16.h>
#include <cstdint>

// ---------------- problem dims ----------------
#define N_OUT   11008
#define K_IN    4096
#define T_TOK   32
#define GROUP   128

// ---------------- tiling ----------------
#define KSPLIT  8
#define GPC     4                       // groups per CTA: 8*4*128 = 4096 = K_IN
#define NTILE   128
#define NBLK    (N_OUT / NTILE)         // 86
#define THREADS 256                     // 8 warps, each owns n-slice of 16

// ---------------- smem layout ----------------
// A buffers: 2 x (32 rows x 128 fp16, 272B pitch)   [tokens x k]
// B buffers: 2 x (128 rows x 128 fp16, 272B pitch)  [k x n]
#define A_SZ1   (32 * 272)              // 8704
#define BOFF    (2 * A_SZ1)             // 17408
#define B_SZ1   (128 * 272)             // 34816
#define SMEM_DYN (BOFF + 2 * B_SZ1)     // 87040 -> 2 CTAs/SM

__device__ float g_part[KSPLIT * T_TOK * N_OUT];

// ---------------- PTX helpers ----------------
__device__ __forceinline__ uint32_t smem_u32(const void* p) {
    uint32_t a;
    asm("{ .reg .u64 t; cvta.to.shared.u64 t, %1; cvt.u32.u64 %0, t; }"
        : "=r"(a) : "l"(p));
    return a;
}
#define LDSMX4(r, addr) \
    asm volatile("ldmatrix.sync.aligned.m8n8.x4.shared.b16 {%0,%1,%2,%3}, [%4];" \
        : "=r"((r)[0]), "=r"((r)[1]), "=r"((r)[2]), "=r"((r)[3]) : "r"(addr))
#define LDSMX4T(r, addr) \
    asm volatile("ldmatrix.sync.aligned.m8n8.x4.trans.shared.b16 {%0,%1,%2,%3}, [%4];" \
        : "=r"((r)[0]), "=r"((r)[1]), "=r"((r)[2]), "=r"((r)[3]) : "r"(addr))

#define MMA16816(d, a, b0, b1) \
    asm volatile("mma.sync.aligned.m16n8k16.row.col.f32.f16.f16.f32 " \
        "{%0,%1,%2,%3}, {%4,%5,%6,%7}, {%8,%9}, {%0,%1,%2,%3};" \
        : "+f"((d)[0]), "+f"((d)[1]), "+f"((d)[2]), "+f"((d)[3]) \
        : "r"((a)[0]), "r"((a)[1]), "r"((a)[2]), "r"((a)[3]), "r"(b0), "r"(b1))

// ---------------- main kernel ----------------
__global__ __launch_bounds__(THREADS, 2)
void awq_mma(const float* __restrict__ x,
             const int*   __restrict__ qw,
             const int*   __restrict__ qz,
             const float* __restrict__ sc)
{
    extern __shared__ __align__(16) char smem[];
    const uint32_t sb = smem_u32(smem);

    const int tid  = threadIdx.x;
    const int lane = tid & 31;
    const int w    = tid >> 5;          // warp 0..7, n-slice w*16
    const int n0   = blockIdx.x * NTILE;
    const int ks   = blockIdx.y;

    // q load geometry: krow = tid>>5 (0..7), int4 col = lane
    const int krow = tid >> 5;
    const int4* qcol = reinterpret_cast<const int4*>(
        qw + (size_t)(ks * GPC * GROUP + krow) * N_OUT + n0) + lane;
    const size_t qrow8 = (size_t)8 * (N_OUT / 4);   // int4 stride: 8 k-rows
    const size_t qgrp  = (size_t)GROUP * (N_OUT / 4);

    // ---- prologue: stage q for group 0 in registers ----
    int4 qr[16];
#pragma unroll
    for (int it = 0; it < 16; it++)
        qr[it] = __ldcs(qcol + (size_t)it * qrow8);

    // ldmatrix lane bases (buffer 0)
    const uint32_t a_lane = sb + (uint32_t)(lane & 15) * 272u
                               + (uint32_t)(lane >> 4) * 16u;
    const uint32_t b_lane = sb + BOFF
        + (uint32_t)(((lane >> 3) & 1) * 8 + (lane & 7)) * 272u
        + (uint32_t)(w * 16 + (lane >> 4) * 8) * 2u;

    const __half2 mhalf = __floats2half2_rn(-1040.0f, -1040.0f);

    float master[2][2][4];
#pragma unroll
    for (int mt = 0; mt < 2; mt++)
#pragma unroll
        for (int nt = 0; nt < 2; nt++)
#pragma unroll
            for (int r = 0; r < 4; r++) master[mt][nt][r] = 0.0f;

    for (int gi = 0; gi < GPC; gi++) {
        const int g   = ks * GPC + gi;
        const int buf = gi & 1;

        // ---- convert qr -> B[buf] fp16 [k][n] via integer magic ----
        // t = q + (0x6410 - z) => halfbits(1024 + (q-z+16)); w = t - 1040
        {
            const int4 z4 = *reinterpret_cast<const int4*>(
                qz + (size_t)g * N_OUT + n0 + lane * 4);
            const int c0 = 0x6410 - z4.x, c1 = 0x6410 - z4.y;
            const int c2 = 0x6410 - z4.z, c3 = 0x6410 - z4.w;
            char* bc = smem + BOFF + buf * B_SZ1 + krow * 272 + lane * 8;
#pragma unroll
            for (int it = 0; it < 16; it++) {
                const int4 q = qr[it];
                const uint32_t p01 = (uint32_t)(q.y + c1) * 65536u + (uint32_t)(q.x + c0);
                const uint32_t p23 = (uint32_t)(q.w + c3) * 65536u + (uint32_t)(q.z + c2);
                __half2 w01 = __hadd2(*reinterpret_cast<const __half2*>(&p01), mhalf);
                __half2 w23 = __hadd2(*reinterpret_cast<const __half2*>(&p23), mhalf);
                uint2 pk;
                pk.x = *reinterpret_cast<uint32_t*>(&w01);
                pk.y = *reinterpret_cast<uint32_t*>(&w23);
                *reinterpret_cast<uint2*>(bc + it * (8 * 272)) = pk;
            }
        }

        // ---- fill A[buf]: x fp32 (L2) -> fp16, rows = tokens ----
        {
            const int t = tid >> 3, seg = tid & 7;
            const float4* xp = reinterpret_cast<const float4*>(
                x + (size_t)t * K_IN + g * GROUP + seg * 16);
            char* ar = smem + buf * A_SZ1 + t * 272 + seg * 32;
#pragma unroll
            for (int q4 = 0; q4 < 4; q4++) {
                const float4 v = xp[q4];
                __half2 h0 = __floats2half2_rn(v.x, v.y);
                __half2 h1 = __floats2half2_rn(v.z, v.w);
                uint2 pk;
                pk.x = *reinterpret_cast<uint32_t*>(&h0);
                pk.y = *reinterpret_cast<uint32_t*>(&h1);
                *reinterpret_cast<uint2*>(ar + q4 * 8) = pk;
            }
        }

        // ---- stage next group's q (regs free after convert) ----
        if (gi + 1 < GPC) {
#pragma unroll
            for (int it = 0; it < 16; it++)
                qr[it] = __ldcs(qcol + (size_t)(gi + 1) * qgrp + (size_t)it * qrow8);
        }

        __syncthreads();       // A[buf], B[buf] visible; buf safe to read

        // ---- MMA: 8 k-steps ----
        float gacc[2][2][4];
#pragma unroll
        for (int mt = 0; mt < 2; mt++)
#pragma unroll
            for (int nt = 0; nt < 2; nt++)
#pragma unroll
                for (int r = 0; r < 4; r++) gacc[mt][nt][r] = 0.0f;

        const uint32_t ab = a_lane + buf * A_SZ1;
        const uint32_t bb = b_lane + buf * B_SZ1;
#pragma unroll
        for (int j = 0; j < 8; j++) {
            uint32_t a0[4], a1[4], b[4];
            LDSMX4(a0, ab + j * 32);
            LDSMX4(a1, ab + 16 * 272 + j * 32);
            LDSMX4T(b, bb + j * (16 * 272));
            MMA16816(gacc[0][0], a0, b[0], b[1]);
            MMA16816(gacc[0][1], a0, b[2], b[3]);
            MMA16816(gacc[1][0], a1, b[0], b[1]);
            MMA16816(gacc[1][1], a1, b[2], b[3]);
        }

        // ---- per-group scale into master acc ----
#pragma unroll
        for (int nt = 0; nt < 2; nt++) {
            const int nn = n0 + w * 16 + nt * 8 + (lane & 3) * 2;
            const float2 s2 = *reinterpret_cast<const float2*>(
                sc + (size_t)g * N_OUT + nn);
#pragma unroll
            for (int mt = 0; mt < 2; mt++) {
                master[mt][nt][0] = fmaf(s2.x, gacc[mt][nt][0], master[mt][nt][0]);
                master[mt][nt][1] = fmaf(s2.y, gacc[mt][nt][1], master[mt][nt][1]);
                master[mt][nt][2] = fmaf(s2.x, gacc[mt][nt][2], master[mt][nt][2]);
                master[mt][nt][3] = fmaf(s2.y, gacc[mt][nt][3], master[mt][nt][3]);
            }
        }
    }

    // ---- write split-K partials ----
    const int mrow = lane >> 2;
#pragma unroll
    for (int mt = 0; mt < 2; mt++)
#pragma unroll
        for (int nt = 0; nt < 2; nt++) {
            const int nn = n0 + w * 16 + nt * 8 + (lane & 3) * 2;
            float* p = g_part + ((size_t)ks * T_TOK + mt * 16 + mrow) * N_OUT + nn;
            *reinterpret_cast<float2*>(p) =
                make_float2(master[mt][nt][0], master[mt][nt][1]);
            *reinterpret_cast<float2*>(p + (size_t)8 * N_OUT) =
                make_float2(master[mt][nt][2], master[mt][nt][3]);
        }
}

__global__ __launch_bounds__(256)
void awq_reduce(const float* __restrict__ bias, float* __restrict__ out)
{
    const int total4 = (T_TOK * N_OUT) / 4;  // 88064
    int i = blockIdx.x * blockDim.x + threadIdx.x;
    if (i >= total4) return;
    const int n4 = i % (N_OUT / 4);

    float4 s = reinterpret_cast<const float4*>(bias)[n4];
    const float4* part4 = reinterpret_cast<const float4*>(g_part);
#pragma unroll
    for (int sp = 0; sp < KSPLIT; sp++) {
        float4 v = part4[(size_t)sp * total4 + i];
        s.x += v.x; s.y += v.y; s.z += v.z; s.w += v.w;
    }
    reinterpret_cast<float4*>(out)[i] = s;
}

extern "C" void kernel_launch(void* const* d_in, const int* in_sizes, int n_in,
                              void* d_out, int out_size)
{
    const float* x    = (const float*)d_in[0];
    const int*   qw   = (const int*)  d_in[1];
    const int*   qz   = (const int*)  d_in[2];
    const float* sc   = (const float*)d_in[3];
    const float* bias = (const float*)d_in[4];
    float*       out  = (float*)d_out;

    // Unconditional (idempotent, capture-legal): no cross-call state.
    cudaFuncSetAttribute(awq_mma, cudaFuncAttributeMaxDynamicSharedMemorySize,
                         SMEM_DYN);

    dim3 grid(NBLK, KSPLIT);
    awq_mma<<<grid, THREADS, SMEM_DYN>>>(x, qw, qz, sc);

    const int total4 = (T_TOK * N_OUT) / 4;
    awq_reduce<<<(total4 + 255) / 256, 256>>>(bias, out);
}